// round 14
// baseline (speedup 1.0000x reference)
#include <cuda_runtime.h>
#include <cuda_fp16.h>
#include <math.h>
#include <stdint.h>

#define N_NODES 100000
#define N_EDGES 1600000
#define IN_DIM 768
#define HIDDEN 256
#define N_CLASSES 3
#define NSPLIT 4

// ---- device scratch (static; no allocation allowed) ----
__device__ float g_dinv[N_NODES];
__device__ __half g_xh[(size_t)N_NODES * IN_DIM];  // x in fp16 (pre-converted)
__device__ __half g_hh[(size_t)N_NODES * HIDDEN];  // h = (x@W1)[i], fp16 (UNSCALED)
__device__ int g_cnt[N_NODES];
__device__ int g_off[N_NODES + 1];
__device__ int g_cur[N_NODES];
__device__ int g_csr[N_EDGES];
__device__ int g_bsum[128];
__device__ int g_bpre[128];
__device__ __half g_w1t[(size_t)HIDDEN * IN_DIM];  // W1^T fp16 [256][768]

// ---- streams + events for pipelining (created pre-main) ----
static cudaStream_t g_s1a, g_s1b, g_s2;
static cudaEvent_t g_ev_fork, g_ev_w1, g_ev_join, g_ev_ga, g_ev_gb;
static cudaEvent_t g_evx[NSPLIT];
namespace {
struct InitStreams {
    InitStreams() {
        cudaStreamCreateWithFlags(&g_s1a, cudaStreamNonBlocking);
        cudaStreamCreateWithFlags(&g_s1b, cudaStreamNonBlocking);
        cudaStreamCreateWithFlags(&g_s2, cudaStreamNonBlocking);
        cudaEventCreateWithFlags(&g_ev_fork, cudaEventDisableTiming);
        cudaEventCreateWithFlags(&g_ev_w1, cudaEventDisableTiming);
        cudaEventCreateWithFlags(&g_ev_join, cudaEventDisableTiming);
        cudaEventCreateWithFlags(&g_ev_ga, cudaEventDisableTiming);
        cudaEventCreateWithFlags(&g_ev_gb, cudaEventDisableTiming);
        for (int i = 0; i < NSPLIT; i++)
            cudaEventCreateWithFlags(&g_evx[i], cudaEventDisableTiming);
    }
};
InitStreams g_init_streams;
}

// ---------------------------------------------------------------------------
// helpers
// ---------------------------------------------------------------------------
__device__ __forceinline__ uint32_t smem_u32(const void* p) {
    uint32_t a;
    asm("{ .reg .u64 t; cvta.to.shared.u64 t, %1; cvt.u32.u64 %0, t; }" : "=r"(a) : "l"(p));
    return a;
}
__device__ __forceinline__ void mma_f16(float* d, const uint32_t* a, const uint32_t* b) {
    asm volatile(
        "mma.sync.aligned.m16n8k16.row.col.f32.f16.f16.f32 "
        "{%0,%1,%2,%3}, {%4,%5,%6,%7}, {%8,%9}, {%0,%1,%2,%3};"
        : "+f"(d[0]), "+f"(d[1]), "+f"(d[2]), "+f"(d[3])
        : "r"(a[0]), "r"(a[1]), "r"(a[2]), "r"(a[3]), "r"(b[0]), "r"(b[1]));
}
__device__ __forceinline__ void ldmat_x4(uint32_t* r, uint32_t addr) {
    asm volatile("ldmatrix.sync.aligned.m8n8.x4.shared.b16 {%0,%1,%2,%3}, [%4];"
                 : "=r"(r[0]), "=r"(r[1]), "=r"(r[2]), "=r"(r[3]) : "r"(addr));
}
__device__ __forceinline__ uint32_t pack_h2(float a, float b) {
    __half2 h = __floats2half2_rn(a, b);
    return *reinterpret_cast<uint32_t*>(&h);
}
#define CP_ASYNC16(dst, src) \
    asm volatile("cp.async.ca.shared.global [%0], [%1], 16;" :: "r"(dst), "l"(src))
#define CP_COMMIT() asm volatile("cp.async.commit_group;" ::: "memory")
#define CP_WAIT0()  asm volatile("cp.async.wait_group 0;" ::: "memory")

// ---------------------------------------------------------------------------
// prep_x chunk: fp32 -> fp16, elems [start, start+count), 8 per thread
// ---------------------------------------------------------------------------
__global__ __launch_bounds__(256) void k_prep_x(const float* __restrict__ x,
                                                int start, int count) {
    int i = (blockIdx.x * blockDim.x + threadIdx.x) * 8;
    if (i >= count) return;
    int g = start + i;
    float4 v0 = *reinterpret_cast<const float4*>(x + g);
    float4 v1 = *reinterpret_cast<const float4*>(x + g + 4);
    uint4 w = make_uint4(pack_h2(v0.x, v0.y), pack_h2(v0.z, v0.w),
                         pack_h2(v1.x, v1.y), pack_h2(v1.z, v1.w));
    *reinterpret_cast<uint4*>(g_xh + g) = w;
}

// ---------------------------------------------------------------------------
// W1 prep (transpose to fp16)
// ---------------------------------------------------------------------------
__global__ void k_prep_w1(const float* __restrict__ W1) {
    int idx = blockIdx.x * blockDim.x + threadIdx.x;
    if (idx >= IN_DIM * HIDDEN) return;
    int k = idx / HIDDEN;
    int nn = idx % HIDDEN;
    g_w1t[(size_t)nn * IN_DIM + k] = __float2half_rn(W1[idx]);
}

// ---------------------------------------------------------------------------
// s2 chain: zero -> cnt -> scan1/2/3 (parallel) -> fill
// ---------------------------------------------------------------------------
__global__ void k_zero_cnt(int n) {
    int i = blockIdx.x * blockDim.x + threadIdx.x;
    if (i < n) g_cnt[i] = 0;
}
__global__ void k_cnt(const int* __restrict__ dst, int E) {
    int i = blockIdx.x * blockDim.x + threadIdx.x;
    if (i < E) atomicAdd(&g_cnt[dst[i]], 1);
}
__global__ __launch_bounds__(1024) void k_scan1(int n) {
    __shared__ int sw[32];
    int b = blockIdx.x, t = threadIdx.x;
    int i = b * 1024 + t;
    int v = (i < n) ? g_cnt[i] : 0;
    int s = v;
#pragma unroll
    for (int o = 16; o > 0; o >>= 1) s += __shfl_down_sync(0xFFFFFFFFu, s, o);
    if ((t & 31) == 0) sw[t >> 5] = s;
    __syncthreads();
    if (t < 32) {
        int x = sw[t];
#pragma unroll
        for (int o = 16; o > 0; o >>= 1) x += __shfl_down_sync(0xFFFFFFFFu, x, o);
        if (t == 0) g_bsum[b] = x;
    }
}
__global__ __launch_bounds__(128) void k_scan2(int nb2) {
    __shared__ int s[128];
    int t = threadIdx.x;
    int v0 = (t < nb2) ? g_bsum[t] : 0;
    s[t] = v0;
    __syncthreads();
#pragma unroll
    for (int o = 1; o < 128; o <<= 1) {
        int u = (t >= o) ? s[t - o] : 0;
        __syncthreads();
        s[t] += u;
        __syncthreads();
    }
    if (t < nb2) g_bpre[t] = s[t] - v0;
}
__global__ __launch_bounds__(1024) void k_scan3(int n) {
    __shared__ int sm[1024];
    int b = blockIdx.x, t = threadIdx.x;
    int i = b * 1024 + t;
    int v = (i < n) ? g_cnt[i] : 0;
    sm[t] = v;
    __syncthreads();
#pragma unroll
    for (int o = 1; o < 1024; o <<= 1) {
        int u = (t >= o) ? sm[t - o] : 0;
        __syncthreads();
        sm[t] += u;
        __syncthreads();
    }
    if (i < n) {
        int incl = sm[t] + g_bpre[b];
        g_off[i + 1] = incl;
        g_cur[i] = incl - v;
        g_dinv[i] = rsqrtf(1.0f + (float)v);
    }
    if (i == 0) g_off[0] = 0;
}
__global__ void k_fill(const int* __restrict__ src, const int* __restrict__ dst, int E) {
    int e = blockIdx.x * blockDim.x + threadIdx.x;
    if (e < E) {
        int d = dst[e];
        int pos = atomicAdd(&g_cur[d], 1);
        g_csr[pos] = src[e];
    }
}

// ---------------------------------------------------------------------------
// fp16 HMMA GEMM chunk: rows [rb0*128, rb0*128 + gridDim.y*128)
//   CTA tile 128x128, 128 threads (4 warps), warp tile 64x64,
//   K chunks of 64, cp.async A+B, 144B row stride, 72KB double-buffer, 2 CTA/SM.
// ---------------------------------------------------------------------------
#define RS 144
#define A_OFF 0
#define B_OFF 18432
#define SMB 36864
#define GEMM_SMEM (2 * SMB)
#define NCH (IN_DIM / 64)   // 12 chunks

extern __shared__ char smem_raw[];

__global__ __launch_bounds__(128, 2) void k_gemm_hmma(int n, int rb0) {
    const uint32_t sb = smem_u32(smem_raw);
    const int tid = threadIdx.x;
    const int wid = tid >> 5;
    const int lane = tid & 31;
    const int wm = wid >> 1;          // 0..1  (x64 rows)
    const int wn = wid & 1;           // 0..1  (x64 cols)
    const int gID = lane >> 2;
    const int tig = lane & 3;
    const int row0 = (rb0 + blockIdx.y) * 128;
    const int col0 = blockIdx.x * 128;

    float acc[4][8][4];
#pragma unroll
    for (int i = 0; i < 4; i++)
#pragma unroll
        for (int j = 0; j < 8; j++)
#pragma unroll
            for (int q = 0; q < 4; q++) acc[i][j][q] = 0.0f;

    // staging: 1 thread per row, 64 halves (128B = 8 x cp.async16) each for A and B
    const int srow = tid;             // 0..127
    const int grow = row0 + srow;
    const bool a_ok = (grow < n);
    const __half* axp = g_xh + (size_t)(a_ok ? grow : 0) * IN_DIM;
    const __half* bptr = g_w1t + (size_t)(col0 + srow) * IN_DIM;
    const uint32_t st_off = (uint32_t)(srow * RS);

    // fragment lane offsets
    const uint32_t a_lo = (uint32_t)((lane & 15) * RS + ((lane & 16) ? 16 : 0));
    const uint32_t b_lo = (uint32_t)(((lane & 7) + ((lane & 16) ? 8 : 0)) * RS + ((lane & 8) ? 16 : 0));

    // ---- prologue: stage chunk 0 into buffer 0 ----
#pragma unroll
    for (int j = 0; j < 8; j++) {
        CP_ASYNC16(sb + A_OFF + st_off + j * 16, axp + j * 8);
        CP_ASYNC16(sb + B_OFF + st_off + j * 16, bptr + j * 8);
    }
    CP_COMMIT();
    CP_WAIT0();
    __syncthreads();

    int buf = 0;
    for (int c = 0; c < NCH; c++) {
        const bool has_next = (c + 1 < NCH);
        const uint32_t bb = sb + (uint32_t)(buf * SMB);

        if (has_next) {
            const int k1 = (c + 1) * 64;
            const uint32_t nb = sb + (uint32_t)((buf ^ 1) * SMB);
#pragma unroll
            for (int j = 0; j < 8; j++) {
                CP_ASYNC16(nb + A_OFF + st_off + j * 16, axp + k1 + j * 8);
                CP_ASYNC16(nb + B_OFF + st_off + j * 16, bptr + k1 + j * 8);
            }
            CP_COMMIT();
        }

        // ---- compute 4 k-steps of 16 ----
#pragma unroll
        for (int ks = 0; ks < 4; ks++) {
            const uint32_t kkb = ks * 32;
            uint32_t bfr[8][2];
#pragma unroll
            for (int p = 0; p < 4; p++) {
                uint32_t r[4];
                ldmat_x4(r, bb + B_OFF + (uint32_t)(wn * 64 + p * 16) * RS + kkb + b_lo);
                bfr[2 * p][0] = r[0]; bfr[2 * p][1] = r[1];
                bfr[2 * p + 1][0] = r[2]; bfr[2 * p + 1][1] = r[3];
            }
#pragma unroll
            for (int mf = 0; mf < 4; mf++) {
                uint32_t ah[4];
                ldmat_x4(ah, bb + A_OFF + (uint32_t)(wm * 64 + mf * 16) * RS + kkb + a_lo);
#pragma unroll
                for (int nf = 0; nf < 8; nf++) mma_f16(acc[mf][nf], ah, bfr[nf]);
            }
        }

        CP_WAIT0();
        __syncthreads();
        buf ^= 1;
    }

    // ---- epilogue: store UNSCALED h as fp16 ----
#pragma unroll
    for (int mf = 0; mf < 4; mf++) {
        int r0 = row0 + wm * 64 + mf * 16 + gID;
        int r1 = r0 + 8;
#pragma unroll
        for (int nf = 0; nf < 8; nf++) {
            int cc = col0 + wn * 64 + nf * 8 + 2 * tig;
            if (r0 < n)
                *reinterpret_cast<__half2*>(g_hh + (size_t)r0 * HIDDEN + cc) =
                    __floats2half2_rn(acc[mf][nf][0], acc[mf][nf][1]);
            if (r1 < n)
                *reinterpret_cast<__half2*>(g_hh + (size_t)r1 * HIDDEN + cc) =
                    __floats2half2_rn(acc[mf][nf][2], acc[mf][nf][3]);
        }
    }
}

// ---------------------------------------------------------------------------
// fused aggregate + finalize (warp per node, fp16 gather)
// ---------------------------------------------------------------------------
__device__ __forceinline__ void acc_row8(float* a, uint4 v, float s) {
    float2 f;
    f = __half22float2(*reinterpret_cast<__half2*>(&v.x)); a[0] = fmaf(s, f.x, a[0]); a[1] = fmaf(s, f.y, a[1]);
    f = __half22float2(*reinterpret_cast<__half2*>(&v.y)); a[2] = fmaf(s, f.x, a[2]); a[3] = fmaf(s, f.y, a[3]);
    f = __half22float2(*reinterpret_cast<__half2*>(&v.z)); a[4] = fmaf(s, f.x, a[4]); a[5] = fmaf(s, f.y, a[5]);
    f = __half22float2(*reinterpret_cast<__half2*>(&v.w)); a[6] = fmaf(s, f.x, a[6]); a[7] = fmaf(s, f.y, a[7]);
}

__global__ __launch_bounds__(256) void k_aggfinal(const float* __restrict__ b1,
                                                  const float* __restrict__ W2,
                                                  const float* __restrict__ b2,
                                                  float* __restrict__ out,
                                                  int n) {
    __shared__ float sW2[HIDDEN * N_CLASSES];
    __shared__ float sb1[HIDDEN];
    for (int i = threadIdx.x; i < HIDDEN * N_CLASSES; i += blockDim.x) sW2[i] = W2[i];
    for (int i = threadIdx.x; i < HIDDEN; i += blockDim.x) sb1[i] = b1[i];
    __syncthreads();

    const int warp = (blockIdx.x * blockDim.x + threadIdx.x) >> 5;
    const int lane = threadIdx.x & 31;
    if (warp >= n) return;

    const int beg = g_off[warp];
    const int end = g_off[warp + 1];
    const float di = g_dinv[warp];

    float a[8] = {0.f, 0.f, 0.f, 0.f, 0.f, 0.f, 0.f, 0.f};
    {
        uint4 v = *(reinterpret_cast<const uint4*>(g_hh + (size_t)warp * HIDDEN) + lane);
        acc_row8(a, v, di);
    }

    int i = beg;
    for (; i + 3 < end; i += 4) {
        int s0 = __ldg(&g_csr[i]);
        int s1 = __ldg(&g_csr[i + 1]);
        int s2 = __ldg(&g_csr[i + 2]);
        int s3 = __ldg(&g_csr[i + 3]);
        float d0 = __ldg(&g_dinv[s0]);
        float d1 = __ldg(&g_dinv[s1]);
        float d2 = __ldg(&g_dinv[s2]);
        float d3 = __ldg(&g_dinv[s3]);
        uint4 v0 = *(reinterpret_cast<const uint4*>(g_hh + (size_t)s0 * HIDDEN) + lane);
        uint4 v1 = *(reinterpret_cast<const uint4*>(g_hh + (size_t)s1 * HIDDEN) + lane);
        uint4 v2 = *(reinterpret_cast<const uint4*>(g_hh + (size_t)s2 * HIDDEN) + lane);
        uint4 v3 = *(reinterpret_cast<const uint4*>(g_hh + (size_t)s3 * HIDDEN) + lane);
        acc_row8(a, v0, d0);
        acc_row8(a, v1, d1);
        acc_row8(a, v2, d2);
        acc_row8(a, v3, d3);
    }
    for (; i < end; i++) {
        int s0 = __ldg(&g_csr[i]);
        float d0 = __ldg(&g_dinv[s0]);
        uint4 v0 = *(reinterpret_cast<const uint4*>(g_hh + (size_t)s0 * HIDDEN) + lane);
        acc_row8(a, v0, d0);
    }

    float acc0 = 0.f, acc1 = 0.f, acc2 = 0.f;
    const int c0 = lane * 8;
#pragma unroll
    for (int j = 0; j < 8; j++) {
        float h = fmaxf(fmaf(di, a[j], sb1[c0 + j]), 0.f);
        acc0 += h * sW2[(c0 + j) * 3 + 0];
        acc1 += h * sW2[(c0 + j) * 3 + 1];
        acc2 += h * sW2[(c0 + j) * 3 + 2];
    }
#pragma unroll
    for (int o = 16; o > 0; o >>= 1) {
        acc0 += __shfl_down_sync(0xFFFFFFFFu, acc0, o);
        acc1 += __shfl_down_sync(0xFFFFFFFFu, acc1, o);
        acc2 += __shfl_down_sync(0xFFFFFFFFu, acc2, o);
    }
    if (lane == 0) {
        float l0 = acc0 + b2[0];
        float l1 = acc1 + b2[1];
        float l2 = acc2 + b2[2];
        float m = fmaxf(l0, fmaxf(l1, l2));
        float se = expf(l0 - m) + expf(l1 - m) + expf(l2 - m);
        float lse = m + logf(se);
        out[(size_t)warp * 3 + 0] = l0 - lse;
        out[(size_t)warp * 3 + 1] = l1 - lse;
        out[(size_t)warp * 3 + 2] = l2 - lse;
    }
}

// ---------------------------------------------------------------------------
extern "C" void kernel_launch(void* const* d_in, const int* in_sizes, int n_in,
                              void* d_out, int out_size) {
    const float* x  = (const float*)d_in[0];
    const int*   ei = (const int*)d_in[1];
    const float* W1 = (const float*)d_in[2];
    const float* b1 = (const float*)d_in[3];
    const float* W2 = (const float*)d_in[4];
    const float* b2 = (const float*)d_in[5];
    float* out = (float*)d_out;

    int n = in_sizes[0] / IN_DIM;
    int E = in_sizes[1] / 2;
    const int* src = ei;
    const int* dst = ei + E;

    cudaFuncSetAttribute(k_gemm_hmma, cudaFuncAttributeMaxDynamicSharedMemorySize, GEMM_SMEM);

    // fork side streams (rooted in default stream via event)
    cudaEventRecord(g_ev_fork, 0);
    cudaStreamWaitEvent(g_s1a, g_ev_fork, 0);
    cudaStreamWaitEvent(g_s1b, g_ev_fork, 0);
    cudaStreamWaitEvent(g_s2, g_ev_fork, 0);

    // chunk geometry
    const int nb = (n + 127) / 128;
    const int cb = (nb + NSPLIT - 1) / NSPLIT;
    int rb[NSPLIT], bl[NSPLIT];
    for (int i = 0; i < NSPLIT; i++) {
        rb[i] = i * cb;
        int rem = nb - rb[i];
        bl[i] = rem > cb ? cb : (rem > 0 ? rem : 0);
    }

    auto launch_prep = [&](int i) {
        if (bl[i] > 0) {
            int start = rb[i] * 128 * IN_DIM;
            int rows = bl[i] * 128;
            if (rb[i] * 128 + rows > n) rows = n - rb[i] * 128;
            int count = rows * IN_DIM;
            k_prep_x<<<(count / 8 + 255) / 256, 256>>>(x, start, count);
        }
        cudaEventRecord(g_evx[i], 0);
    };
    auto launch_gemm = [&](int i) {
        if (bl[i] <= 0) return;
        cudaStream_t s = (i & 1) ? g_s1b : g_s1a;
        cudaStreamWaitEvent(s, g_evx[i], 0);
        dim3 gg(HIDDEN / 128, bl[i]);
        k_gemm_hmma<<<gg, 128, GEMM_SMEM, s>>>(n, rb[i]);
    };

    launch_prep(0);                                                       // #1
    k_prep_w1<<<(IN_DIM * HIDDEN + 255) / 256, 256, 0, g_s2>>>(W1);       // #2
    cudaEventRecord(g_ev_w1, g_s2);
    cudaStreamWaitEvent(g_s1a, g_ev_w1, 0);
    cudaStreamWaitEvent(g_s1b, g_ev_w1, 0);
    launch_prep(1);                                                       // #3
    launch_gemm(0);                                                       // #4 (profiled)
    launch_prep(2);                                                       // #5
    launch_gemm(1);                                                       // #6
    launch_prep(3);                                                       // #7
    launch_gemm(2);                                                       // #8
    launch_gemm(3);                                                       // #9

    // s2: CSR chain (parallel scan), hidden under the GEMM pipeline
    const int nb2 = (n + 1023) / 1024;
    k_zero_cnt<<<(n + 255) / 256, 256, 0, g_s2>>>(n);
    k_cnt<<<(E + 255) / 256, 256, 0, g_s2>>>(dst, E);
    k_scan1<<<nb2, 1024, 0, g_s2>>>(n);
    k_scan2<<<1, 128, 0, g_s2>>>(nb2);
    k_scan3<<<nb2, 1024, 0, g_s2>>>(n);
    k_fill<<<(E + 255) / 256, 256, 0, g_s2>>>(src, dst, E);
    cudaEventRecord(g_ev_join, g_s2);

    // join all pipelines, then fused aggregate+finalize
    cudaEventRecord(g_ev_ga, g_s1a);
    cudaEventRecord(g_ev_gb, g_s1b);
    cudaStreamWaitEvent(0, g_ev_ga, 0);
    cudaStreamWaitEvent(0, g_ev_gb, 0);
    cudaStreamWaitEvent(0, g_ev_join, 0);
    int fblocks = (n * 32 + 255) / 256;
    k_aggfinal<<<fblocks, 256>>>(b1, W2, b2, out, n);
}

// round 15
// speedup vs baseline: 1.1980x; 1.1980x over previous
#include <cuda_runtime.h>
#include <cuda_fp16.h>
#include <math.h>
#include <stdint.h>

#define N_NODES 100000
#define N_EDGES 1600000
#define IN_DIM 768
#define HIDDEN 256
#define N_CLASSES 3
#define NSPLIT 4

// ---- device scratch (static; no allocation allowed) ----
__device__ float g_dinv[N_NODES];
__device__ __half g_xh[(size_t)N_NODES * IN_DIM];  // x in fp16 (pre-converted)
__device__ __half g_hh[(size_t)N_NODES * HIDDEN];  // h = (x@W1)[i], fp16 (UNSCALED)
__device__ int g_cnt[N_NODES];
__device__ int g_off[N_NODES + 1];
__device__ int g_cur[N_NODES];
__device__ int g_csr[N_EDGES];
__device__ int g_bsum[128];
__device__ int g_bpre[128];
__device__ __half g_w1t[(size_t)HIDDEN * IN_DIM];  // W1^T fp16 [256][768]

// ---- streams + events (created pre-main); GEMM high-pri, prep low-pri ----
static cudaStream_t g_s1a, g_s1b, g_s2, g_s3;
static cudaEvent_t g_ev_fork, g_ev_w1, g_ev_join, g_ev_ga, g_ev_gb;
static cudaEvent_t g_evx[NSPLIT];
namespace {
struct InitStreams {
    InitStreams() {
        int lo = 0, hi = 0;
        cudaDeviceGetStreamPriorityRange(&lo, &hi);  // hi = highest (most negative)
        cudaStreamCreateWithPriority(&g_s1a, cudaStreamNonBlocking, hi);
        cudaStreamCreateWithPriority(&g_s1b, cudaStreamNonBlocking, hi);
        cudaStreamCreateWithFlags(&g_s2, cudaStreamNonBlocking);
        cudaStreamCreateWithPriority(&g_s3, cudaStreamNonBlocking, lo);  // prep_x (backfill)
        cudaEventCreateWithFlags(&g_ev_fork, cudaEventDisableTiming);
        cudaEventCreateWithFlags(&g_ev_w1, cudaEventDisableTiming);
        cudaEventCreateWithFlags(&g_ev_join, cudaEventDisableTiming);
        cudaEventCreateWithFlags(&g_ev_ga, cudaEventDisableTiming);
        cudaEventCreateWithFlags(&g_ev_gb, cudaEventDisableTiming);
        for (int i = 0; i < NSPLIT; i++)
            cudaEventCreateWithFlags(&g_evx[i], cudaEventDisableTiming);
    }
};
InitStreams g_init_streams;
}

// ---------------------------------------------------------------------------
// helpers
// ---------------------------------------------------------------------------
__device__ __forceinline__ uint32_t smem_u32(const void* p) {
    uint32_t a;
    asm("{ .reg .u64 t; cvta.to.shared.u64 t, %1; cvt.u32.u64 %0, t; }" : "=r"(a) : "l"(p));
    return a;
}
__device__ __forceinline__ void mma_f16(float* d, const uint32_t* a, const uint32_t* b) {
    asm volatile(
        "mma.sync.aligned.m16n8k16.row.col.f32.f16.f16.f32 "
        "{%0,%1,%2,%3}, {%4,%5,%6,%7}, {%8,%9}, {%0,%1,%2,%3};"
        : "+f"(d[0]), "+f"(d[1]), "+f"(d[2]), "+f"(d[3])
        : "r"(a[0]), "r"(a[1]), "r"(a[2]), "r"(a[3]), "r"(b[0]), "r"(b[1]));
}
__device__ __forceinline__ void ldmat_x4(uint32_t* r, uint32_t addr) {
    asm volatile("ldmatrix.sync.aligned.m8n8.x4.shared.b16 {%0,%1,%2,%3}, [%4];"
                 : "=r"(r[0]), "=r"(r[1]), "=r"(r[2]), "=r"(r[3]) : "r"(addr));
}
__device__ __forceinline__ uint32_t pack_h2(float a, float b) {
    __half2 h = __floats2half2_rn(a, b);
    return *reinterpret_cast<uint32_t*>(&h);
}
#define CP_ASYNC16(dst, src) \
    asm volatile("cp.async.ca.shared.global [%0], [%1], 16;" :: "r"(dst), "l"(src))
#define CP_COMMIT() asm volatile("cp.async.commit_group;" ::: "memory")
#define CP_WAIT0()  asm volatile("cp.async.wait_group 0;" ::: "memory")

// ---------------------------------------------------------------------------
// prep_x chunk: fp32 -> fp16, elems [start, start+count), 8 per thread
// ---------------------------------------------------------------------------
__global__ __launch_bounds__(256) void k_prep_x(const float* __restrict__ x,
                                                int start, int count) {
    int i = (blockIdx.x * blockDim.x + threadIdx.x) * 8;
    if (i >= count) return;
    int g = start + i;
    float4 v0 = *reinterpret_cast<const float4*>(x + g);
    float4 v1 = *reinterpret_cast<const float4*>(x + g + 4);
    uint4 w = make_uint4(pack_h2(v0.x, v0.y), pack_h2(v0.z, v0.w),
                         pack_h2(v1.x, v1.y), pack_h2(v1.z, v1.w));
    *reinterpret_cast<uint4*>(g_xh + g) = w;
}

// ---------------------------------------------------------------------------
// W1 prep (transpose to fp16)
// ---------------------------------------------------------------------------
__global__ void k_prep_w1(const float* __restrict__ W1) {
    int idx = blockIdx.x * blockDim.x + threadIdx.x;
    if (idx >= IN_DIM * HIDDEN) return;
    int k = idx / HIDDEN;
    int nn = idx % HIDDEN;
    g_w1t[(size_t)nn * IN_DIM + k] = __float2half_rn(W1[idx]);
}

// ---------------------------------------------------------------------------
// s2 chain: zero -> cnt -> scan1/2/3 (parallel) -> fill
// ---------------------------------------------------------------------------
__global__ void k_zero_cnt(int n) {
    int i = blockIdx.x * blockDim.x + threadIdx.x;
    if (i < n) g_cnt[i] = 0;
}
__global__ void k_cnt(const int* __restrict__ dst, int E) {
    int i = blockIdx.x * blockDim.x + threadIdx.x;
    if (i < E) atomicAdd(&g_cnt[dst[i]], 1);
}
__global__ __launch_bounds__(1024) void k_scan1(int n) {
    __shared__ int sw[32];
    int b = blockIdx.x, t = threadIdx.x;
    int i = b * 1024 + t;
    int v = (i < n) ? g_cnt[i] : 0;
    int s = v;
#pragma unroll
    for (int o = 16; o > 0; o >>= 1) s += __shfl_down_sync(0xFFFFFFFFu, s, o);
    if ((t & 31) == 0) sw[t >> 5] = s;
    __syncthreads();
    if (t < 32) {
        int x = sw[t];
#pragma unroll
        for (int o = 16; o > 0; o >>= 1) x += __shfl_down_sync(0xFFFFFFFFu, x, o);
        if (t == 0) g_bsum[b] = x;
    }
}
__global__ __launch_bounds__(128) void k_scan2(int nb2) {
    __shared__ int s[128];
    int t = threadIdx.x;
    int v0 = (t < nb2) ? g_bsum[t] : 0;
    s[t] = v0;
    __syncthreads();
#pragma unroll
    for (int o = 1; o < 128; o <<= 1) {
        int u = (t >= o) ? s[t - o] : 0;
        __syncthreads();
        s[t] += u;
        __syncthreads();
    }
    if (t < nb2) g_bpre[t] = s[t] - v0;
}
__global__ __launch_bounds__(1024) void k_scan3(int n) {
    __shared__ int sm[1024];
    int b = blockIdx.x, t = threadIdx.x;
    int i = b * 1024 + t;
    int v = (i < n) ? g_cnt[i] : 0;
    sm[t] = v;
    __syncthreads();
#pragma unroll
    for (int o = 1; o < 1024; o <<= 1) {
        int u = (t >= o) ? sm[t - o] : 0;
        __syncthreads();
        sm[t] += u;
        __syncthreads();
    }
    if (i < n) {
        int incl = sm[t] + g_bpre[b];
        g_off[i + 1] = incl;
        g_cur[i] = incl - v;
        g_dinv[i] = rsqrtf(1.0f + (float)v);
    }
    if (i == 0) g_off[0] = 0;
}
__global__ void k_fill(const int* __restrict__ src, const int* __restrict__ dst, int E) {
    int e = blockIdx.x * blockDim.x + threadIdx.x;
    if (e < E) {
        int d = dst[e];
        int pos = atomicAdd(&g_cur[d], 1);
        g_csr[pos] = src[e];
    }
}

// ---------------------------------------------------------------------------
// fp16 HMMA GEMM chunk (R11/R13 geometry — LOCKED):
//   CTA tile 128x128, 256 thr, warp tile 64x32, K chunks of 64,
//   cp.async A+B, 144B row stride, 72KB double-buffer, 2 CTA/SM.
// ---------------------------------------------------------------------------
#define RS 144
#define A_OFF 0
#define B_OFF 18432
#define SMB 36864
#define GEMM_SMEM (2 * SMB)
#define NCH (IN_DIM / 64)   // 12 chunks

extern __shared__ char smem_raw[];

__global__ __launch_bounds__(256, 2) void k_gemm_hmma(int n, int rb0) {
    const uint32_t sb = smem_u32(smem_raw);
    const int tid = threadIdx.x;
    const int wid = tid >> 5;
    const int lane = tid & 31;
    const int wm = wid >> 2;
    const int wn = wid & 3;
    const int gID = lane >> 2;
    const int tig = lane & 3;
    const int row0 = (rb0 + blockIdx.y) * 128;
    const int col0 = blockIdx.x * 128;

    float acc[4][4][4];
#pragma unroll
    for (int i = 0; i < 4; i++)
#pragma unroll
        for (int j = 0; j < 4; j++)
#pragma unroll
            for (int q = 0; q < 4; q++) acc[i][j][q] = 0.0f;

    const int srow = tid >> 1;
    const int shalf = tid & 1;
    const int grow = row0 + srow;
    const bool a_ok = (grow < n);
    const __half* axp = g_xh + (size_t)(a_ok ? grow : 0) * IN_DIM + shalf * 32;
    const __half* bptr = g_w1t + (size_t)(col0 + srow) * IN_DIM + shalf * 32;
    const uint32_t st_off = (uint32_t)(srow * RS + shalf * 64);

    const uint32_t a_lo = (uint32_t)((lane & 15) * RS + ((lane & 16) ? 16 : 0));
    const uint32_t b_lo = (uint32_t)(((lane & 7) + ((lane & 16) ? 8 : 0)) * RS + ((lane & 8) ? 16 : 0));

#pragma unroll
    for (int j = 0; j < 4; j++) {
        CP_ASYNC16(sb + A_OFF + st_off + j * 16, axp + j * 8);
        CP_ASYNC16(sb + B_OFF + st_off + j * 16, bptr + j * 8);
    }
    CP_COMMIT();
    CP_WAIT0();
    __syncthreads();

    int buf = 0;
    for (int c = 0; c < NCH; c++) {
        const bool has_next = (c + 1 < NCH);
        const uint32_t bb = sb + (uint32_t)(buf * SMB);

        if (has_next) {
            const int k1 = (c + 1) * 64;
            const uint32_t nb = sb + (uint32_t)((buf ^ 1) * SMB);
#pragma unroll
            for (int j = 0; j < 4; j++) {
                CP_ASYNC16(nb + A_OFF + st_off + j * 16, axp + k1 + j * 8);
                CP_ASYNC16(nb + B_OFF + st_off + j * 16, bptr + k1 + j * 8);
            }
            CP_COMMIT();
        }

#pragma unroll
        for (int ks = 0; ks < 4; ks++) {
            const uint32_t kkb = ks * 32;
            uint32_t bfr[4][2];
            {
                uint32_t r[4];
                ldmat_x4(r, bb + B_OFF + (uint32_t)(wn * 32) * RS + kkb + b_lo);
                bfr[0][0] = r[0]; bfr[0][1] = r[1]; bfr[1][0] = r[2]; bfr[1][1] = r[3];
                ldmat_x4(r, bb + B_OFF + (uint32_t)(wn * 32 + 16) * RS + kkb + b_lo);
                bfr[2][0] = r[0]; bfr[2][1] = r[1]; bfr[3][0] = r[2]; bfr[3][1] = r[3];
            }
#pragma unroll
            for (int mf = 0; mf < 4; mf++) {
                uint32_t ah[4];
                ldmat_x4(ah, bb + A_OFF + (uint32_t)(wm * 64 + mf * 16) * RS + kkb + a_lo);
#pragma unroll
                for (int nf = 0; nf < 4; nf++) mma_f16(acc[mf][nf], ah, bfr[nf]);
            }
        }

        CP_WAIT0();
        __syncthreads();
        buf ^= 1;
    }

#pragma unroll
    for (int mf = 0; mf < 4; mf++) {
        int r0 = row0 + wm * 64 + mf * 16 + gID;
        int r1 = r0 + 8;
#pragma unroll
        for (int nf = 0; nf < 4; nf++) {
            int cc = col0 + wn * 32 + nf * 8 + 2 * tig;
            if (r0 < n)
                *reinterpret_cast<__half2*>(g_hh + (size_t)r0 * HIDDEN + cc) =
                    __floats2half2_rn(acc[mf][nf][0], acc[mf][nf][1]);
            if (r1 < n)
                *reinterpret_cast<__half2*>(g_hh + (size_t)r1 * HIDDEN + cc) =
                    __floats2half2_rn(acc[mf][nf][2], acc[mf][nf][3]);
        }
    }
}

// ---------------------------------------------------------------------------
// fused aggregate + finalize (warp per node, fp16 gather)
// ---------------------------------------------------------------------------
__device__ __forceinline__ void acc_row8(float* a, uint4 v, float s) {
    float2 f;
    f = __half22float2(*reinterpret_cast<__half2*>(&v.x)); a[0] = fmaf(s, f.x, a[0]); a[1] = fmaf(s, f.y, a[1]);
    f = __half22float2(*reinterpret_cast<__half2*>(&v.y)); a[2] = fmaf(s, f.x, a[2]); a[3] = fmaf(s, f.y, a[3]);
    f = __half22float2(*reinterpret_cast<__half2*>(&v.z)); a[4] = fmaf(s, f.x, a[4]); a[5] = fmaf(s, f.y, a[5]);
    f = __half22float2(*reinterpret_cast<__half2*>(&v.w)); a[6] = fmaf(s, f.x, a[6]); a[7] = fmaf(s, f.y, a[7]);
}

__global__ __launch_bounds__(256) void k_aggfinal(const float* __restrict__ b1,
                                                  const float* __restrict__ W2,
                                                  const float* __restrict__ b2,
                                                  float* __restrict__ out,
                                                  int n) {
    __shared__ float sW2[HIDDEN * N_CLASSES];
    __shared__ float sb1[HIDDEN];
    for (int i = threadIdx.x; i < HIDDEN * N_CLASSES; i += blockDim.x) sW2[i] = W2[i];
    for (int i = threadIdx.x; i < HIDDEN; i += blockDim.x) sb1[i] = b1[i];
    __syncthreads();

    const int warp = (blockIdx.x * blockDim.x + threadIdx.x) >> 5;
    const int lane = threadIdx.x & 31;
    if (warp >= n) return;

    const int beg = g_off[warp];
    const int end = g_off[warp + 1];
    const float di = g_dinv[warp];

    float a[8] = {0.f, 0.f, 0.f, 0.f, 0.f, 0.f, 0.f, 0.f};
    {
        uint4 v = *(reinterpret_cast<const uint4*>(g_hh + (size_t)warp * HIDDEN) + lane);
        acc_row8(a, v, di);
    }

    int i = beg;
    for (; i + 3 < end; i += 4) {
        int s0 = __ldg(&g_csr[i]);
        int s1 = __ldg(&g_csr[i + 1]);
        int s2 = __ldg(&g_csr[i + 2]);
        int s3 = __ldg(&g_csr[i + 3]);
        float d0 = __ldg(&g_dinv[s0]);
        float d1 = __ldg(&g_dinv[s1]);
        float d2 = __ldg(&g_dinv[s2]);
        float d3 = __ldg(&g_dinv[s3]);
        uint4 v0 = *(reinterpret_cast<const uint4*>(g_hh + (size_t)s0 * HIDDEN) + lane);
        uint4 v1 = *(reinterpret_cast<const uint4*>(g_hh + (size_t)s1 * HIDDEN) + lane);
        uint4 v2 = *(reinterpret_cast<const uint4*>(g_hh + (size_t)s2 * HIDDEN) + lane);
        uint4 v3 = *(reinterpret_cast<const uint4*>(g_hh + (size_t)s3 * HIDDEN) + lane);
        acc_row8(a, v0, d0);
        acc_row8(a, v1, d1);
        acc_row8(a, v2, d2);
        acc_row8(a, v3, d3);
    }
    for (; i < end; i++) {
        int s0 = __ldg(&g_csr[i]);
        float d0 = __ldg(&g_dinv[s0]);
        uint4 v0 = *(reinterpret_cast<const uint4*>(g_hh + (size_t)s0 * HIDDEN) + lane);
        acc_row8(a, v0, d0);
    }

    float acc0 = 0.f, acc1 = 0.f, acc2 = 0.f;
    const int c0 = lane * 8;
#pragma unroll
    for (int j = 0; j < 8; j++) {
        float h = fmaxf(fmaf(di, a[j], sb1[c0 + j]), 0.f);
        acc0 += h * sW2[(c0 + j) * 3 + 0];
        acc1 += h * sW2[(c0 + j) * 3 + 1];
        acc2 += h * sW2[(c0 + j) * 3 + 2];
    }
#pragma unroll
    for (int o = 16; o > 0; o >>= 1) {
        acc0 += __shfl_down_sync(0xFFFFFFFFu, acc0, o);
        acc1 += __shfl_down_sync(0xFFFFFFFFu, acc1, o);
        acc2 += __shfl_down_sync(0xFFFFFFFFu, acc2, o);
    }
    if (lane == 0) {
        float l0 = acc0 + b2[0];
        float l1 = acc1 + b2[1];
        float l2 = acc2 + b2[2];
        float m = fmaxf(l0, fmaxf(l1, l2));
        float se = expf(l0 - m) + expf(l1 - m) + expf(l2 - m);
        float lse = m + logf(se);
        out[(size_t)warp * 3 + 0] = l0 - lse;
        out[(size_t)warp * 3 + 1] = l1 - lse;
        out[(size_t)warp * 3 + 2] = l2 - lse;
    }
}

// ---------------------------------------------------------------------------
extern "C" void kernel_launch(void* const* d_in, const int* in_sizes, int n_in,
                              void* d_out, int out_size) {
    const float* x  = (const float*)d_in[0];
    const int*   ei = (const int*)d_in[1];
    const float* W1 = (const float*)d_in[2];
    const float* b1 = (const float*)d_in[3];
    const float* W2 = (const float*)d_in[4];
    const float* b2 = (const float*)d_in[5];
    float* out = (float*)d_out;

    int n = in_sizes[0] / IN_DIM;
    int E = in_sizes[1] / 2;
    const int* src = ei;
    const int* dst = ei + E;

    cudaFuncSetAttribute(k_gemm_hmma, cudaFuncAttributeMaxDynamicSharedMemorySize, GEMM_SMEM);

    // fork side streams (rooted in default stream via event)
    cudaEventRecord(g_ev_fork, 0);
    cudaStreamWaitEvent(g_s1a, g_ev_fork, 0);
    cudaStreamWaitEvent(g_s1b, g_ev_fork, 0);
    cudaStreamWaitEvent(g_s2, g_ev_fork, 0);
    cudaStreamWaitEvent(g_s3, g_ev_fork, 0);

    // chunk geometry
    const int nb = (n + 127) / 128;
    const int cb = (nb + NSPLIT - 1) / NSPLIT;
    int rb[NSPLIT], bl[NSPLIT];
    for (int i = 0; i < NSPLIT; i++) {
        rb[i] = i * cb;
        int rem = nb - rb[i];
        bl[i] = rem > cb ? cb : (rem > 0 ? rem : 0);
    }

    // prep_x chunks on LOW-priority stream g_s3 (backfill under GEMM)
    auto launch_prep = [&](int i) {
        if (bl[i] > 0) {
            int start = rb[i] * 128 * IN_DIM;
            int rows = bl[i] * 128;
            if (rb[i] * 128 + rows > n) rows = n - rb[i] * 128;
            int count = rows * IN_DIM;
            k_prep_x<<<(count / 8 + 255) / 256, 256, 0, g_s3>>>(x, start, count);
        }
        cudaEventRecord(g_evx[i], g_s3);
    };
    // GEMM chunks alternate between two HIGH-priority streams
    auto launch_gemm = [&](int i) {
        if (bl[i] <= 0) return;
        cudaStream_t s = (i & 1) ? g_s1b : g_s1a;
        cudaStreamWaitEvent(s, g_evx[i], 0);
        dim3 gg(HIDDEN / 128, bl[i]);
        k_gemm_hmma<<<gg, 256, GEMM_SMEM, s>>>(n, rb[i]);
    };

    launch_prep(0);                                                       // #1
    k_prep_w1<<<(IN_DIM * HIDDEN + 255) / 256, 256, 0, g_s2>>>(W1);       // #2
    cudaEventRecord(g_ev_w1, g_s2);
    cudaStreamWaitEvent(g_s1a, g_ev_w1, 0);
    cudaStreamWaitEvent(g_s1b, g_ev_w1, 0);
    launch_prep(1);                                                       // #3
    launch_gemm(0);                                                       // #4 (profiled)
    launch_prep(2);                                                       // #5
    launch_gemm(1);                                                       // #6
    launch_prep(3);                                                       // #7
    launch_gemm(2);                                                       // #8
    launch_gemm(3);                                                       // #9

    // s2: CSR chain (parallel scan), hidden under the GEMM pipeline
    const int nb2 = (n + 1023) / 1024;
    k_zero_cnt<<<(n + 255) / 256, 256, 0, g_s2>>>(n);
    k_cnt<<<(E + 255) / 256, 256, 0, g_s2>>>(dst, E);
    k_scan1<<<nb2, 1024, 0, g_s2>>>(n);
    k_scan2<<<1, 128, 0, g_s2>>>(nb2);
    k_scan3<<<nb2, 1024, 0, g_s2>>>(n);
    k_fill<<<(E + 255) / 256, 256, 0, g_s2>>>(src, dst, E);
    cudaEventRecord(g_ev_join, g_s2);

    // join all pipelines, then fused aggregate+finalize
    cudaEventRecord(g_ev_ga, g_s1a);
    cudaEventRecord(g_ev_gb, g_s1b);
    cudaStreamWaitEvent(0, g_ev_ga, 0);
    cudaStreamWaitEvent(0, g_ev_gb, 0);
    cudaStreamWaitEvent(0, g_ev_join, 0);
    int fblocks = (n * 32 + 255) / 256;
    k_aggfinal<<<fblocks, 256>>>(b1, W2, b2, out, n);
}